// round 1
// baseline (speedup 1.0000x reference)
#include <cuda_runtime.h>
#include <math.h>

#define T 1024
#define H 1280
#define NH 10
#define HD 128
#define EI 896
#define NEXP 64
#define TOPK 6
#define SHF 1792
#define NPAIR (T*TOPK)

// ---------------- device scratch (module globals; no cudaMalloc) ----------------
static __device__ float g_h1[T*H];
static __device__ float g_q[T*H];
static __device__ float g_k[T*H];
static __device__ float g_v[T*H];
static __device__ float g_scores[NH*T*T];          // 42 MB
static __device__ float g_attnout[T*H];
static __device__ float g_hres[T*H];
static __device__ float g_h2[T*H];
static __device__ float g_sg[T*SHF];
static __device__ float g_su[T*SHF];
static __device__ float g_shared[T*H];
static __device__ float g_gpeT[(size_t)NEXP*H*EI]; // 293 MB, [e][h][i]
static __device__ float g_upeT[(size_t)NEXP*H*EI]; // [e][h][i]
static __device__ float g_dpeT[(size_t)NEXP*EI*H]; // [e][i][h]
static __device__ float g_act[(size_t)NPAIR*EI];   // 22 MB
static __device__ float g_pairout[(size_t)NPAIR*H];// 31.5 MB
static __device__ int   g_cnt[NEXP];
static __device__ int   g_off[NEXP];
static __device__ int   g_cur[NEXP];
static __device__ int   g_tokE[NPAIR];
static __device__ float g_tokW[NPAIR];
static __device__ int   g_pairTok[NPAIR];
static __device__ float g_pairW[NPAIR];
static __device__ int   g_pairPos[NPAIR];

// ---------------- RMSNorm ----------------
__global__ void rms_kernel(const float* __restrict__ x, const float* __restrict__ w,
                           float* __restrict__ out) {
    int t = blockIdx.x;
    const float* xr = x + (long)t*H;
    __shared__ float red[256];
    float s = 0.f;
    for (int i = threadIdx.x; i < H; i += 256) { float v = xr[i]; s += v*v; }
    red[threadIdx.x] = s; __syncthreads();
    for (int k = 128; k > 0; k >>= 1) {
        if (threadIdx.x < k) red[threadIdx.x] += red[threadIdx.x + k];
        __syncthreads();
    }
    float r = rsqrtf(red[0]/(float)H + 1e-6f);
    for (int i = threadIdx.x; i < H; i += 256) out[(long)t*H + i] = w[i]*xr[i]*r;
}

// ---------------- generic fp32 GEMM: C = alpha*A@B (+res), tiles 64x64x16 ----------------
// A[M,K] lda. transB==0: B[K,N] ldb ; transB==1: B[N,K] ldb. Batched via gridDim.z strides.
__global__ void __launch_bounds__(128)
gemm_kernel(const float* __restrict__ A, int lda, long sA,
            const float* __restrict__ B, int ldb, long sB, int transB,
            float* __restrict__ C, int ldc, long sC,
            const float* __restrict__ res, long sR,
            int M, int N, int K, float alpha) {
    long bz = blockIdx.z;
    A += bz*sA; B += bz*sB; C += bz*sC; if (res) res += bz*sR;
    int m0 = blockIdx.y*64, n0 = blockIdx.x*64;
    __shared__ float As[64*20];
    __shared__ float Bs[16*68];
    int tid = threadIdx.x;
    int tx = tid & 15, ty = tid >> 4;
    float acc[8][4] = {};
    for (int k0 = 0; k0 < K; k0 += 16) {
        #pragma unroll
        for (int i = 0; i < 2; i++) {
            int f4 = tid + i*128; int m = f4 >> 2, kq = (f4 & 3) << 2;
            float4 v = *(const float4*)&A[(long)(m0+m)*lda + k0 + kq];
            *(float4*)&As[m*20 + kq] = v;
        }
        if (!transB) {
            #pragma unroll
            for (int i = 0; i < 8; i++) {
                int idx = tid + i*128; int kk = idx >> 6, n = idx & 63;
                Bs[kk*68 + n] = B[(long)(k0+kk)*ldb + n0 + n];
            }
        } else {
            #pragma unroll
            for (int i = 0; i < 2; i++) {
                int f4 = tid + i*128; int n = f4 >> 2, kq = (f4 & 3) << 2;
                float4 v = *(const float4*)&B[(long)(n0+n)*ldb + k0 + kq];
                Bs[(kq+0)*68 + n] = v.x; Bs[(kq+1)*68 + n] = v.y;
                Bs[(kq+2)*68 + n] = v.z; Bs[(kq+3)*68 + n] = v.w;
            }
        }
        __syncthreads();
        #pragma unroll
        for (int kk = 0; kk < 16; kk++) {
            float a[8];
            #pragma unroll
            for (int i = 0; i < 8; i++) a[i] = As[(ty*8+i)*20 + kk];
            float4 b4 = *(const float4*)&Bs[kk*68 + tx*4];
            float b[4] = {b4.x, b4.y, b4.z, b4.w};
            #pragma unroll
            for (int i = 0; i < 8; i++)
                #pragma unroll
                for (int j = 0; j < 4; j++) acc[i][j] += a[i]*b[j];
        }
        __syncthreads();
    }
    #pragma unroll
    for (int i = 0; i < 8; i++) {
        int m = m0 + ty*8 + i;
        #pragma unroll
        for (int j = 0; j < 4; j++) {
            int n = n0 + tx*4 + j;
            float v = alpha * acc[i][j];
            if (res) v += res[(long)m*ldc + n];
            C[(long)m*ldc + n] = v;
        }
    }
}

// ---------------- RoPE on q,k (in place) ----------------
__global__ void rope_kernel() {
    int t = blockIdx.x, tid = threadIdx.x;
    __shared__ float cs[64], sn[64];
    if (tid < 64) {
        float inv = powf(10000.0f, -(float)tid / 64.0f);
        float fr = (float)t * inv;
        cs[tid] = cosf(fr); sn[tid] = sinf(fr);
    }
    __syncthreads();
    for (int idx = tid; idx < NH*64; idx += 256) {
        int hh = idx >> 6, j = idx & 63;
        long b = (long)t*H + hh*HD;
        float c = cs[j], s = sn[j];
        float q1 = g_q[b+j], q2 = g_q[b+j+64];
        g_q[b+j]    = q1*c - q2*s;
        g_q[b+j+64] = q2*c + q1*s;
        float k1 = g_k[b+j], k2 = g_k[b+j+64];
        g_k[b+j]    = k1*c - k2*s;
        g_k[b+j+64] = k2*c + k1*s;
    }
}

// ---------------- causal softmax over scores rows (zeros future so PV uses full K) ---------
__global__ void attn_softmax() {
    int t = blockIdx.x, hh = blockIdx.y, tid = threadIdx.x;
    float* row = g_scores + ((long)hh*T + t)*(long)T;
    int len = t + 1;
    __shared__ float red[256];
    float mx = -3.0e38f;
    for (int i = tid; i < len; i += 256) mx = fmaxf(mx, row[i]);
    red[tid] = mx; __syncthreads();
    for (int s = 128; s > 0; s >>= 1) { if (tid < s) red[tid] = fmaxf(red[tid], red[tid+s]); __syncthreads(); }
    mx = red[0]; __syncthreads();
    float sum = 0.f;
    for (int i = tid; i < len; i += 256) { float e = expf(row[i]-mx); row[i] = e; sum += e; }
    red[tid] = sum; __syncthreads();
    for (int s = 128; s > 0; s >>= 1) { if (tid < s) red[tid] += red[tid+s]; __syncthreads(); }
    float inv = 1.0f / red[0];
    for (int i = tid; i < len; i += 256) row[i] *= inv;
    for (int i = len + tid; i < T; i += 256) row[i] = 0.f;
}

// ---------------- expert-last transpose: in[R][C][64] -> out[64][R][C] ----------------
__global__ void transpose_e(const float* __restrict__ in, float* __restrict__ out, int R, int C) {
    int r = blockIdx.y;
    int c0 = blockIdx.x * 32;
    __shared__ float tile[64*33];
    const float* src = in + ((long)r*C + c0)*64;
    for (int i = threadIdx.x; i < 2048; i += 256) {
        int ci = i >> 6, e = i & 63;
        tile[e*33 + ci] = src[i];
    }
    __syncthreads();
    for (int i = threadIdx.x; i < 2048; i += 256) {
        int e = i >> 5, ci = i & 31;
        out[(long)e*R*C + (long)r*C + c0 + ci] = tile[e*33 + ci];
    }
}

// ---------------- router: logits, softmax, top-6, renorm ----------------
__global__ void zero_cnt_kernel() { if (threadIdx.x < NEXP) g_cnt[threadIdx.x] = 0; }

__global__ void router_kernel(const float* __restrict__ gw) {
    int t = blockIdx.x, e = threadIdx.x;
    const float* hr = g_h2 + (long)t*H;
    float s = 0.f;
    for (int h = 0; h < H; h++) s += hr[h] * gw[h*NEXP + e];
    __shared__ float probs[NEXP];
    probs[e] = s;
    __syncthreads();
    if (e == 0) {
        float mx = -3e38f;
        for (int i = 0; i < NEXP; i++) mx = fmaxf(mx, probs[i]);
        float sum = 0.f;
        for (int i = 0; i < NEXP; i++) { probs[i] = expf(probs[i]-mx); sum += probs[i]; }
        float inv = 1.f/sum;
        for (int i = 0; i < NEXP; i++) probs[i] *= inv;
        int ti[TOPK]; float tw[TOPK]; float ws = 0.f;
        for (int j = 0; j < TOPK; j++) {
            int bi = 0; float bv = -1.f;
            for (int i = 0; i < NEXP; i++) if (probs[i] > bv) { bv = probs[i]; bi = i; }
            ti[j] = bi; tw[j] = bv; ws += bv; probs[bi] = -2.f;
        }
        float wi = 1.f/ws;
        for (int j = 0; j < TOPK; j++) {
            g_tokE[t*TOPK+j] = ti[j];
            g_tokW[t*TOPK+j] = tw[j]*wi;
            atomicAdd(&g_cnt[ti[j]], 1);
        }
    }
}

__global__ void prefix_kernel() {
    if (threadIdx.x == 0) {
        int s = 0;
        for (int e = 0; e < NEXP; e++) { g_off[e] = s; g_cur[e] = s; s += g_cnt[e]; }
    }
}

__global__ void scatter_kernel() {
    int i = blockIdx.x*256 + threadIdx.x;
    if (i < NPAIR) {
        int e = g_tokE[i];
        int pos = atomicAdd(&g_cur[e], 1);
        g_pairTok[pos] = i / TOPK;
        g_pairW[pos]   = g_tokW[i];
        g_pairPos[i]   = pos;
    }
}

// ---------------- MoE pass 1: act = silu(h2@gpe_e) * (h2@upe_e), rows gathered per expert ---
__global__ void __launch_bounds__(128) moe_pass1() {
    int e = blockIdx.z;
    int cnt = g_cnt[e];
    int m0 = blockIdx.y * 64;
    if (m0 >= cnt) return;
    int n0 = blockIdx.x * 64;
    int base = g_off[e];
    const float* Bg = g_gpeT + (size_t)e*H*EI;
    const float* Bu = g_upeT + (size_t)e*H*EI;
    __shared__ int stok[64];
    __shared__ float As[64*20];
    __shared__ float Bs1[16*68];
    __shared__ float Bs2[16*68];
    int tid = threadIdx.x;
    if (tid < 64) stok[tid] = (m0 + tid < cnt) ? g_pairTok[base + m0 + tid] : -1;
    __syncthreads();
    int tx = tid & 15, ty = tid >> 4;
    float accG[8][4] = {}, accU[8][4] = {};
    for (int k0 = 0; k0 < H; k0 += 16) {
        #pragma unroll
        for (int i = 0; i < 2; i++) {
            int f4 = tid + i*128; int m = f4 >> 2, kq = (f4 & 3) << 2;
            int tok = stok[m];
            float4 v = (tok >= 0) ? *(const float4*)&g_h2[(long)tok*H + k0 + kq]
                                  : make_float4(0.f,0.f,0.f,0.f);
            *(float4*)&As[m*20 + kq] = v;
        }
        #pragma unroll
        for (int i = 0; i < 8; i++) {
            int idx = tid + i*128; int kk = idx >> 6, n = idx & 63;
            Bs1[kk*68 + n] = Bg[(long)(k0+kk)*EI + n0 + n];
            Bs2[kk*68 + n] = Bu[(long)(k0+kk)*EI + n0 + n];
        }
        __syncthreads();
        #pragma unroll
        for (int kk = 0; kk < 16; kk++) {
            float a[8];
            #pragma unroll
            for (int i = 0; i < 8; i++) a[i] = As[(ty*8+i)*20 + kk];
            float4 b1 = *(const float4*)&Bs1[kk*68 + tx*4];
            float4 b2 = *(const float4*)&Bs2[kk*68 + tx*4];
            float bg[4] = {b1.x,b1.y,b1.z,b1.w};
            float bu[4] = {b2.x,b2.y,b2.z,b2.w};
            #pragma unroll
            for (int i = 0; i < 8; i++) {
                #pragma unroll
                for (int j = 0; j < 4; j++) {
                    accG[i][j] += a[i]*bg[j];
                    accU[i][j] += a[i]*bu[j];
                }
            }
        }
        __syncthreads();
    }
    #pragma unroll
    for (int i = 0; i < 8; i++) {
        int m = m0 + ty*8 + i;
        if (m < cnt) {
            float* dst = g_act + (long)(base+m)*EI + n0 + tx*4;
            #pragma unroll
            for (int j = 0; j < 4; j++) {
                float g = accG[i][j], u = accU[i][j];
                dst[j] = (g / (1.f + expf(-g))) * u;
            }
        }
    }
}

// ---------------- MoE pass 2: pairout = act @ dpe_e ----------------
__global__ void __launch_bounds__(128) moe_pass2() {
    int e = blockIdx.z;
    int cnt = g_cnt[e];
    int m0 = blockIdx.y * 64;
    if (m0 >= cnt) return;
    int n0 = blockIdx.x * 64;
    int base = g_off[e];
    const float* Bm = g_dpeT + (size_t)e*EI*H;
    __shared__ float As[64*20];
    __shared__ float Bs[16*68];
    int tid = threadIdx.x, tx = tid & 15, ty = tid >> 4;
    float acc[8][4] = {};
    for (int k0 = 0; k0 < EI; k0 += 16) {
        #pragma unroll
        for (int i = 0; i < 2; i++) {
            int f4 = tid + i*128; int m = f4 >> 2, kq = (f4 & 3) << 2;
            float4 v = (m0 + m < cnt) ? *(const float4*)&g_act[(long)(base+m0+m)*EI + k0 + kq]
                                      : make_float4(0.f,0.f,0.f,0.f);
            *(float4*)&As[m*20 + kq] = v;
        }
        #pragma unroll
        for (int i = 0; i < 8; i++) {
            int idx = tid + i*128; int kk = idx >> 6, n = idx & 63;
            Bs[kk*68 + n] = Bm[(long)(k0+kk)*H + n0 + n];
        }
        __syncthreads();
        #pragma unroll
        for (int kk = 0; kk < 16; kk++) {
            float a[8];
            #pragma unroll
            for (int i = 0; i < 8; i++) a[i] = As[(ty*8+i)*20 + kk];
            float4 b4 = *(const float4*)&Bs[kk*68 + tx*4];
            float b[4] = {b4.x,b4.y,b4.z,b4.w};
            #pragma unroll
            for (int i = 0; i < 8; i++)
                #pragma unroll
                for (int j = 0; j < 4; j++) acc[i][j] += a[i]*b[j];
        }
        __syncthreads();
    }
    #pragma unroll
    for (int i = 0; i < 8; i++) {
        int m = m0 + ty*8 + i;
        if (m < cnt) {
            float* dst = g_pairout + (long)(base+m)*H + n0 + tx*4;
            #pragma unroll
            for (int j = 0; j < 4; j++) dst[j] = acc[i][j];
        }
    }
}

// ---------------- shared-FFN activation ----------------
__global__ void silumul_kernel(float* __restrict__ g, const float* __restrict__ u, int n) {
    int i = blockIdx.x*256 + threadIdx.x;
    if (i < n) {
        float x = g[i];
        g[i] = (x / (1.f + expf(-x))) * u[i];
    }
}

// ---------------- final combine: out = hres + shared + sum_j w_j * pairout ----------------
__global__ void combine_kernel(float* __restrict__ out) {
    int t = blockIdx.x;
    int pos[TOPK]; float w[TOPK];
    #pragma unroll
    for (int j = 0; j < TOPK; j++) {
        pos[j] = g_pairPos[t*TOPK + j];
        w[j]   = g_pairW[pos[j]];
    }
    for (int h = threadIdx.x; h < H; h += 256) {
        float s = g_hres[(long)t*H + h] + g_shared[(long)t*H + h];
        #pragma unroll
        for (int j = 0; j < TOPK; j++)
            s += w[j] * g_pairout[(long)pos[j]*H + h];
        out[(long)t*H + h] = s;
    }
}

// ---------------- launch ----------------
extern "C" void kernel_launch(void* const* d_in, const int* in_sizes, int n_in,
                              void* d_out, int out_size) {
    (void)in_sizes; (void)n_in; (void)out_size;
    const float* x       = (const float*)d_in[0];
    const float* ln1     = (const float*)d_in[1];
    const float* ln2     = (const float*)d_in[2];
    const float* Wq      = (const float*)d_in[3];
    const float* Wk      = (const float*)d_in[4];
    const float* Wv      = (const float*)d_in[5];
    const float* Wo      = (const float*)d_in[6];
    const float* gate_w  = (const float*)d_in[7];
    const float* gpe     = (const float*)d_in[8];
    const float* upe     = (const float*)d_in[9];
    const float* dpe     = (const float*)d_in[10];
    const float* sh_gate = (const float*)d_in[11];
    const float* sh_up   = (const float*)d_in[12];
    const float* sh_down = (const float*)d_in[13];
    float* out = (float*)d_out;

    float *h1p,*qp,*kp,*vp,*scoresp,*attnp,*hresp,*h2p,*sgp,*sup,*sharedp,*gpeTp,*upeTp,*dpeTp;
    cudaGetSymbolAddress((void**)&h1p,     g_h1);
    cudaGetSymbolAddress((void**)&qp,      g_q);
    cudaGetSymbolAddress((void**)&kp,      g_k);
    cudaGetSymbolAddress((void**)&vp,      g_v);
    cudaGetSymbolAddress((void**)&scoresp, g_scores);
    cudaGetSymbolAddress((void**)&attnp,   g_attnout);
    cudaGetSymbolAddress((void**)&hresp,   g_hres);
    cudaGetSymbolAddress((void**)&h2p,     g_h2);
    cudaGetSymbolAddress((void**)&sgp,     g_sg);
    cudaGetSymbolAddress((void**)&sup,     g_su);
    cudaGetSymbolAddress((void**)&sharedp, g_shared);
    cudaGetSymbolAddress((void**)&gpeTp,   g_gpeT);
    cudaGetSymbolAddress((void**)&upeTp,   g_upeT);
    cudaGetSymbolAddress((void**)&dpeTp,   g_dpeT);

    const float inv_sqrt_hd = 0.08838834764831845f;

    // attention branch
    rms_kernel<<<T, 256>>>(x, ln1, h1p);
    gemm_kernel<<<dim3(H/64, T/64, 1), 128>>>(h1p, H, 0, Wq, H, 0, 0, qp, H, 0, nullptr, 0, T, H, H, 1.f);
    gemm_kernel<<<dim3(H/64, T/64, 1), 128>>>(h1p, H, 0, Wk, H, 0, 0, kp, H, 0, nullptr, 0, T, H, H, 1.f);
    gemm_kernel<<<dim3(H/64, T/64, 1), 128>>>(h1p, H, 0, Wv, H, 0, 0, vp, H, 0, nullptr, 0, T, H, H, 1.f);
    rope_kernel<<<T, 256>>>();
    gemm_kernel<<<dim3(T/64, T/64, NH), 128>>>(qp, H, HD, kp, H, HD, 1,
                                               scoresp, T, (long)T*T, nullptr, 0,
                                               T, T, HD, inv_sqrt_hd);
    attn_softmax<<<dim3(T, NH), 256>>>();
    gemm_kernel<<<dim3(HD/64, T/64, NH), 128>>>(scoresp, T, (long)T*T, vp, H, HD, 0,
                                                attnp, H, HD, nullptr, 0,
                                                T, HD, T, 1.f);
    gemm_kernel<<<dim3(H/64, T/64, 1), 128>>>(attnp, H, 0, Wo, H, 0, 0, hresp, H, 0, x, 0, T, H, H, 1.f);

    // MoE branch
    rms_kernel<<<T, 256>>>(hresp, ln2, h2p);
    transpose_e<<<dim3(EI/32, H), 256>>>(gpe, gpeTp, H, EI);
    transpose_e<<<dim3(EI/32, H), 256>>>(upe, upeTp, H, EI);
    transpose_e<<<dim3(H/32, EI), 256>>>(dpe, dpeTp, EI, H);
    zero_cnt_kernel<<<1, 64>>>();
    router_kernel<<<T, 64>>>(gate_w);
    prefix_kernel<<<1, 32>>>();
    scatter_kernel<<<(NPAIR + 255)/256, 256>>>();
    moe_pass1<<<dim3(EI/64, T/64, NEXP), 128>>>();
    moe_pass2<<<dim3(H/64, T/64, NEXP), 128>>>();

    // shared FFN
    gemm_kernel<<<dim3(SHF/64, T/64, 1), 128>>>(h2p, H, 0, sh_gate, SHF, 0, 0, sgp, SHF, 0, nullptr, 0, T, SHF, H, 1.f);
    gemm_kernel<<<dim3(SHF/64, T/64, 1), 128>>>(h2p, H, 0, sh_up,   SHF, 0, 0, sup, SHF, 0, nullptr, 0, T, SHF, H, 1.f);
    silumul_kernel<<<(T*SHF + 255)/256, 256>>>(sgp, sup, T*SHF);
    gemm_kernel<<<dim3(H/64, T/64, 1), 128>>>(sgp, SHF, 0, sh_down, H, 0, 0, sharedp, H, 0, nullptr, 0, T, H, SHF, 1.f);

    // combine
    combine_kernel<<<T, 256>>>(out);
}

// round 2
// speedup vs baseline: 1.8447x; 1.8447x over previous
#include <cuda_runtime.h>
#include <math.h>

#define T 1024
#define H 1280
#define NH 10
#define HD 128
#define EI 896
#define NEXP 64
#define TOPK 6
#define SHF 1792
#define NPAIR (T*TOPK)

// ---------------- device scratch ----------------
static __device__ float g_h1[T*H];
static __device__ float g_q[T*H];
static __device__ float g_k[T*H];
static __device__ float g_v[T*H];
static __device__ float g_scores[NH*T*T];
static __device__ float g_attnout[T*H];
static __device__ float g_hres[T*H];
static __device__ float g_h2[T*H];
static __device__ float g_sg[T*SHF];
static __device__ float g_su[T*SHF];
static __device__ float g_shared[T*H];
static __device__ float g_gpeT[(size_t)NEXP*H*EI];
static __device__ float g_upeT[(size_t)NEXP*H*EI];
static __device__ float g_dpeT[(size_t)NEXP*EI*H];
static __device__ float g_act[(size_t)NPAIR*EI];
static __device__ float g_pairout[(size_t)NPAIR*H];
static __device__ int   g_cnt[NEXP];
static __device__ int   g_off[NEXP];
static __device__ int   g_cur[NEXP];
static __device__ int   g_tokE[NPAIR];
static __device__ float g_tokW[NPAIR];
static __device__ int   g_pairTok[NPAIR];
static __device__ float g_pairW[NPAIR];
static __device__ int   g_pairPos[NPAIR];

// ---------------- helpers ----------------
__device__ __forceinline__ unsigned f2tf(float f) {
    unsigned r; asm("cvt.rna.tf32.f32 %0, %1;" : "=r"(r) : "f"(f)); return r;
}
__device__ __forceinline__ void mma_tf32(float4& c, const unsigned a[4], const unsigned b[2]) {
    asm volatile("mma.sync.aligned.m16n8k8.row.col.f32.tf32.tf32.f32 "
        "{%0,%1,%2,%3}, {%4,%5,%6,%7}, {%8,%9}, {%0,%1,%2,%3};"
        : "+f"(c.x), "+f"(c.y), "+f"(c.z), "+f"(c.w)
        : "r"(a[0]), "r"(a[1]), "r"(a[2]), "r"(a[3]), "r"(b[0]), "r"(b[1]));
}

#define ASTRIDE 36   // (4g+tig)%32 == lane -> conflict free
#define BSTRIDE 72   // (8tig+g)%32 unique -> conflict free

// ---------------- RMSNorm ----------------
__global__ void rms_kernel(const float* __restrict__ x, const float* __restrict__ w,
                           float* __restrict__ out) {
    int t = blockIdx.x;
    const float* xr = x + (long)t*H;
    __shared__ float red[256];
    float s = 0.f;
    for (int i = threadIdx.x; i < H; i += 256) { float v = xr[i]; s += v*v; }
    red[threadIdx.x] = s; __syncthreads();
    for (int k = 128; k > 0; k >>= 1) {
        if (threadIdx.x < k) red[threadIdx.x] += red[threadIdx.x + k];
        __syncthreads();
    }
    float r = rsqrtf(red[0]/(float)H + 1e-6f);
    for (int i = threadIdx.x; i < H; i += 256) out[(long)t*H + i] = w[i]*xr[i]*r;
}

// ---------------- generic tf32 tensor-core GEMM: C = alpha*A@B (+res) -------------
// tiles 64x64x32, 128 threads, 4 warps (2x2), warp tile 32x32.
__global__ void __launch_bounds__(128)
gemm_tc(const float* __restrict__ A, int lda, long sA,
        const float* __restrict__ B, int ldb, long sB, int transB,
        float* __restrict__ C, int ldc, long sC,
        const float* __restrict__ res, long sR,
        int M, int N, int K, float alpha, int causal) {
    int m0 = blockIdx.y*64, n0 = blockIdx.x*64;
    if (causal && n0 > m0 + 63) return;
    long bz = blockIdx.z;
    A += bz*sA; B += bz*sB; C += bz*sC; if (res) res += bz*sR;
    __shared__ unsigned As[64*ASTRIDE];
    __shared__ unsigned Bs[32*BSTRIDE];
    int tid = threadIdx.x;
    int lane = tid & 31, warpId = tid >> 5;
    int g = lane >> 2, tig = lane & 3;
    int warp_m = (warpId & 1) * 32, warp_n = (warpId >> 1) * 32;
    float4 acc[2][4];
    #pragma unroll
    for (int i = 0; i < 2; i++)
        #pragma unroll
        for (int j = 0; j < 4; j++) acc[i][j] = make_float4(0.f,0.f,0.f,0.f);

    for (int k0 = 0; k0 < K; k0 += 32) {
        // A tile 64x32
        #pragma unroll
        for (int i = 0; i < 4; i++) {
            int f4 = tid + i*128; int m = f4 >> 3, kq = (f4 & 7) << 2;
            float4 v = *(const float4*)&A[(long)(m0+m)*lda + k0 + kq];
            uint4 u = { f2tf(v.x), f2tf(v.y), f2tf(v.z), f2tf(v.w) };
            *(uint4*)&As[m*ASTRIDE + kq] = u;
        }
        // B tile 32x64 -> Bs[k][n]
        if (!transB) {
            #pragma unroll
            for (int i = 0; i < 4; i++) {
                int f4 = tid + i*128; int k = f4 >> 4, nq = (f4 & 15) << 2;
                float4 v = *(const float4*)&B[(long)(k0+k)*ldb + n0 + nq];
                uint4 u = { f2tf(v.x), f2tf(v.y), f2tf(v.z), f2tf(v.w) };
                *(uint4*)&Bs[k*BSTRIDE + nq] = u;
            }
        } else {
            #pragma unroll
            for (int i = 0; i < 4; i++) {
                int f4 = tid + i*128; int n = f4 >> 3, kq = (f4 & 7) << 2;
                float4 v = *(const float4*)&B[(long)(n0+n)*ldb + k0 + kq];
                Bs[(kq+0)*BSTRIDE + n] = f2tf(v.x);
                Bs[(kq+1)*BSTRIDE + n] = f2tf(v.y);
                Bs[(kq+2)*BSTRIDE + n] = f2tf(v.z);
                Bs[(kq+3)*BSTRIDE + n] = f2tf(v.w);
            }
        }
        __syncthreads();
        #pragma unroll
        for (int kk = 0; kk < 32; kk += 8) {
            unsigned a[2][4], b[4][2];
            #pragma unroll
            for (int mi = 0; mi < 2; mi++) {
                int rb = warp_m + mi*16 + g;
                a[mi][0] = As[rb*ASTRIDE + kk + tig];
                a[mi][1] = As[(rb+8)*ASTRIDE + kk + tig];
                a[mi][2] = As[rb*ASTRIDE + kk + tig + 4];
                a[mi][3] = As[(rb+8)*ASTRIDE + kk + tig + 4];
            }
            #pragma unroll
            for (int ni = 0; ni < 4; ni++) {
                int col = warp_n + ni*8 + g;
                b[ni][0] = Bs[(kk+tig)*BSTRIDE + col];
                b[ni][1] = Bs[(kk+tig+4)*BSTRIDE + col];
            }
            #pragma unroll
            for (int mi = 0; mi < 2; mi++)
                #pragma unroll
                for (int ni = 0; ni < 4; ni++) mma_tf32(acc[mi][ni], a[mi], b[ni]);
        }
        __syncthreads();
    }
    #pragma unroll
    for (int mi = 0; mi < 2; mi++) {
        #pragma unroll
        for (int ni = 0; ni < 4; ni++) {
            int row = m0 + warp_m + mi*16 + g;
            int col = n0 + warp_n + ni*8 + 2*tig;
            float4 c = acc[mi][ni];
            float2 v0 = { alpha*c.x, alpha*c.y };
            float2 v1 = { alpha*c.z, alpha*c.w };
            if (res) {
                float2 r0 = *(const float2*)&res[(long)row*ldc + col];
                float2 r1 = *(const float2*)&res[(long)(row+8)*ldc + col];
                v0.x += r0.x; v0.y += r0.y; v1.x += r1.x; v1.y += r1.y;
            }
            *(float2*)&C[(long)row*ldc + col] = v0;
            *(float2*)&C[(long)(row+8)*ldc + col] = v1;
        }
    }
}

// ---------------- RoPE ----------------
__global__ void rope_kernel() {
    int t = blockIdx.x, tid = threadIdx.x;
    __shared__ float cs[64], sn[64];
    if (tid < 64) {
        float inv = powf(10000.0f, -(float)tid / 64.0f);
        float fr = (float)t * inv;
        cs[tid] = cosf(fr); sn[tid] = sinf(fr);
    }
    __syncthreads();
    for (int idx = tid; idx < NH*64; idx += 256) {
        int hh = idx >> 6, j = idx & 63;
        long b = (long)t*H + hh*HD;
        float c = cs[j], s = sn[j];
        float q1 = g_q[b+j], q2 = g_q[b+j+64];
        g_q[b+j]    = q1*c - q2*s;
        g_q[b+j+64] = q2*c + q1*s;
        float k1 = g_k[b+j], k2 = g_k[b+j+64];
        g_k[b+j]    = k1*c - k2*s;
        g_k[b+j+64] = k2*c + k1*s;
    }
}

// ---------------- causal softmax ----------------
__global__ void attn_softmax() {
    int t = blockIdx.x, hh = blockIdx.y, tid = threadIdx.x;
    float* row = g_scores + ((long)hh*T + t)*(long)T;
    int len = t + 1;
    __shared__ float red[256];
    float mx = -3.0e38f;
    for (int i = tid; i < len; i += 256) mx = fmaxf(mx, row[i]);
    red[tid] = mx; __syncthreads();
    for (int s = 128; s > 0; s >>= 1) { if (tid < s) red[tid] = fmaxf(red[tid], red[tid+s]); __syncthreads(); }
    mx = red[0]; __syncthreads();
    float sum = 0.f;
    for (int i = tid; i < len; i += 256) { float e = expf(row[i]-mx); row[i] = e; sum += e; }
    red[tid] = sum; __syncthreads();
    for (int s = 128; s > 0; s >>= 1) { if (tid < s) red[tid] += red[tid+s]; __syncthreads(); }
    float inv = 1.0f / red[0];
    for (int i = tid; i < len; i += 256) row[i] *= inv;
    for (int i = len + tid; i < T; i += 256) row[i] = 0.f;
}

// ---------------- expert-last transpose: in[R][C][64] -> out[64][R][C] ----------------
__global__ void transpose_e(const float* __restrict__ in, float* __restrict__ out, int R, int C) {
    int r = blockIdx.y;
    int c0 = blockIdx.x * 32;
    __shared__ float tile[64*33];
    const float* src = in + ((long)r*C + c0)*64;
    for (int i = threadIdx.x; i < 2048; i += 256) {
        int ci = i >> 6, e = i & 63;
        tile[e*33 + ci] = src[i];
    }
    __syncthreads();
    for (int i = threadIdx.x; i < 2048; i += 256) {
        int e = i >> 5, ci = i & 31;
        out[(long)e*R*C + (long)r*C + c0 + ci] = tile[e*33 + ci];
    }
}

// ---------------- router ----------------
__global__ void zero_cnt_kernel() { if (threadIdx.x < NEXP) g_cnt[threadIdx.x] = 0; }

__global__ void router_kernel(const float* __restrict__ gw) {
    int t = blockIdx.x, e = threadIdx.x;
    const float* hr = g_h2 + (long)t*H;
    float s = 0.f;
    for (int h = 0; h < H; h++) s += hr[h] * gw[h*NEXP + e];
    __shared__ float probs[NEXP];
    probs[e] = s;
    __syncthreads();
    if (e == 0) {
        float mx = -3e38f;
        for (int i = 0; i < NEXP; i++) mx = fmaxf(mx, probs[i]);
        float sum = 0.f;
        for (int i = 0; i < NEXP; i++) { probs[i] = expf(probs[i]-mx); sum += probs[i]; }
        float inv = 1.f/sum;
        for (int i = 0; i < NEXP; i++) probs[i] *= inv;
        int ti[TOPK]; float tw[TOPK]; float ws = 0.f;
        for (int j = 0; j < TOPK; j++) {
            int bi = 0; float bv = -1.f;
            for (int i = 0; i < NEXP; i++) if (probs[i] > bv) { bv = probs[i]; bi = i; }
            ti[j] = bi; tw[j] = bv; ws += bv; probs[bi] = -2.f;
        }
        float wi = 1.f/ws;
        for (int j = 0; j < TOPK; j++) {
            g_tokE[t*TOPK+j] = ti[j];
            g_tokW[t*TOPK+j] = tw[j]*wi;
            atomicAdd(&g_cnt[ti[j]], 1);
        }
    }
}

__global__ void prefix_kernel() {
    if (threadIdx.x == 0) {
        int s = 0;
        for (int e = 0; e < NEXP; e++) { g_off[e] = s; g_cur[e] = s; s += g_cnt[e]; }
    }
}

__global__ void scatter_kernel() {
    int i = blockIdx.x*256 + threadIdx.x;
    if (i < NPAIR) {
        int e = g_tokE[i];
        int pos = atomicAdd(&g_cur[e], 1);
        g_pairTok[pos] = i / TOPK;
        g_pairW[pos]   = g_tokW[i];
        g_pairPos[i]   = pos;
    }
}

// ---------------- MoE pass 1 (tensor core) ----------------
__global__ void __launch_bounds__(128) moe_pass1() {
    int e = blockIdx.z;
    int cnt = g_cnt[e];
    int m0 = blockIdx.y * 64;
    if (m0 >= cnt) return;
    int n0 = blockIdx.x * 64;
    int base = g_off[e];
    const float* Bg = g_gpeT + (size_t)e*H*EI;
    const float* Bu = g_upeT + (size_t)e*H*EI;
    __shared__ int stok[64];
    __shared__ unsigned As[64*ASTRIDE];
    __shared__ unsigned Bs1[32*BSTRIDE];
    __shared__ unsigned Bs2[32*BSTRIDE];
    int tid = threadIdx.x;
    int lane = tid & 31, warpId = tid >> 5;
    int g = lane >> 2, tig = lane & 3;
    int warp_m = (warpId & 1) * 32, warp_n = (warpId >> 1) * 32;
    if (tid < 64) stok[tid] = (m0 + tid < cnt) ? g_pairTok[base + m0 + tid] : -1;
    __syncthreads();
    float4 accG[2][4], accU[2][4];
    #pragma unroll
    for (int i = 0; i < 2; i++)
        #pragma unroll
        for (int j = 0; j < 4; j++) { accG[i][j] = make_float4(0,0,0,0); accU[i][j] = make_float4(0,0,0,0); }

    for (int k0 = 0; k0 < H; k0 += 32) {
        #pragma unroll
        for (int i = 0; i < 4; i++) {
            int f4 = tid + i*128; int m = f4 >> 3, kq = (f4 & 7) << 2;
            int tok = stok[m];
            float4 v = (tok >= 0) ? *(const float4*)&g_h2[(long)tok*H + k0 + kq]
                                  : make_float4(0,0,0,0);
            uint4 u = { f2tf(v.x), f2tf(v.y), f2tf(v.z), f2tf(v.w) };
            *(uint4*)&As[m*ASTRIDE + kq] = u;
        }
        #pragma unroll
        for (int i = 0; i < 4; i++) {
            int f4 = tid + i*128; int k = f4 >> 4, nq = (f4 & 15) << 2;
            float4 v1 = *(const float4*)&Bg[(long)(k0+k)*EI + n0 + nq];
            float4 v2 = *(const float4*)&Bu[(long)(k0+k)*EI + n0 + nq];
            uint4 u1 = { f2tf(v1.x), f2tf(v1.y), f2tf(v1.z), f2tf(v1.w) };
            uint4 u2 = { f2tf(v2.x), f2tf(v2.y), f2tf(v2.z), f2tf(v2.w) };
            *(uint4*)&Bs1[k*BSTRIDE + nq] = u1;
            *(uint4*)&Bs2[k*BSTRIDE + nq] = u2;
        }
        __syncthreads();
        #pragma unroll
        for (int kk = 0; kk < 32; kk += 8) {
            unsigned a[2][4], b1[4][2], b2[4][2];
            #pragma unroll
            for (int mi = 0; mi < 2; mi++) {
                int rb = warp_m + mi*16 + g;
                a[mi][0] = As[rb*ASTRIDE + kk + tig];
                a[mi][1] = As[(rb+8)*ASTRIDE + kk + tig];
                a[mi][2] = As[rb*ASTRIDE + kk + tig + 4];
                a[mi][3] = As[(rb+8)*ASTRIDE + kk + tig + 4];
            }
            #pragma unroll
            for (int ni = 0; ni < 4; ni++) {
                int col = warp_n + ni*8 + g;
                b1[ni][0] = Bs1[(kk+tig)*BSTRIDE + col];
                b1[ni][1] = Bs1[(kk+tig+4)*BSTRIDE + col];
                b2[ni][0] = Bs2[(kk+tig)*BSTRIDE + col];
                b2[ni][1] = Bs2[(kk+tig+4)*BSTRIDE + col];
            }
            #pragma unroll
            for (int mi = 0; mi < 2; mi++)
                #pragma unroll
                for (int ni = 0; ni < 4; ni++) {
                    mma_tf32(accG[mi][ni], a[mi], b1[ni]);
                    mma_tf32(accU[mi][ni], a[mi], b2[ni]);
                }
        }
        __syncthreads();
    }
    #pragma unroll
    for (int mi = 0; mi < 2; mi++) {
        #pragma unroll
        for (int ni = 0; ni < 4; ni++) {
            int mrow = warp_m + mi*16 + g;
            int col = n0 + warp_n + ni*8 + 2*tig;
            float4 cg = accG[mi][ni], cu = accU[mi][ni];
            if (m0 + mrow < cnt) {
                float g0 = cg.x, g1 = cg.y;
                float2 v = { (g0/(1.f+expf(-g0)))*cu.x, (g1/(1.f+expf(-g1)))*cu.y };
                *(float2*)&g_act[(long)(base+m0+mrow)*EI + col] = v;
            }
            if (m0 + mrow + 8 < cnt) {
                float g0 = cg.z, g1 = cg.w;
                float2 v = { (g0/(1.f+expf(-g0)))*cu.z, (g1/(1.f+expf(-g1)))*cu.w };
                *(float2*)&g_act[(long)(base+m0+mrow+8)*EI + col] = v;
            }
        }
    }
}

// ---------------- MoE pass 2 (tensor core) ----------------
__global__ void __launch_bounds__(128) moe_pass2() {
    int e = blockIdx.z;
    int cnt = g_cnt[e];
    int m0 = blockIdx.y * 64;
    if (m0 >= cnt) return;
    int n0 = blockIdx.x * 64;
    int base = g_off[e];
    const float* Bm = g_dpeT + (size_t)e*EI*H;
    __shared__ unsigned As[64*ASTRIDE];
    __shared__ unsigned Bs[32*BSTRIDE];
    int tid = threadIdx.x;
    int lane = tid & 31, warpId = tid >> 5;
    int g = lane >> 2, tig = lane & 3;
    int warp_m = (warpId & 1) * 32, warp_n = (warpId >> 1) * 32;
    float4 acc[2][4];
    #pragma unroll
    for (int i = 0; i < 2; i++)
        #pragma unroll
        for (int j = 0; j < 4; j++) acc[i][j] = make_float4(0,0,0,0);

    for (int k0 = 0; k0 < EI; k0 += 32) {
        #pragma unroll
        for (int i = 0; i < 4; i++) {
            int f4 = tid + i*128; int m = f4 >> 3, kq = (f4 & 7) << 2;
            float4 v = (m0 + m < cnt) ? *(const float4*)&g_act[(long)(base+m0+m)*EI + k0 + kq]
                                      : make_float4(0,0,0,0);
            uint4 u = { f2tf(v.x), f2tf(v.y), f2tf(v.z), f2tf(v.w) };
            *(uint4*)&As[m*ASTRIDE + kq] = u;
        }
        #pragma unroll
        for (int i = 0; i < 4; i++) {
            int f4 = tid + i*128; int k = f4 >> 4, nq = (f4 & 15) << 2;
            float4 v = *(const float4*)&Bm[(long)(k0+k)*H + n0 + nq];
            uint4 u = { f2tf(v.x), f2tf(v.y), f2tf(v.z), f2tf(v.w) };
            *(uint4*)&Bs[k*BSTRIDE + nq] = u;
        }
        __syncthreads();
        #pragma unroll
        for (int kk = 0; kk < 32; kk += 8) {
            unsigned a[2][4], b[4][2];
            #pragma unroll
            for (int mi = 0; mi < 2; mi++) {
                int rb = warp_m + mi*16 + g;
                a[mi][0] = As[rb*ASTRIDE + kk + tig];
                a[mi][1] = As[(rb+8)*ASTRIDE + kk + tig];
                a[mi][2] = As[rb*ASTRIDE + kk + tig + 4];
                a[mi][3] = As[(rb+8)*ASTRIDE + kk + tig + 4];
            }
            #pragma unroll
            for (int ni = 0; ni < 4; ni++) {
                int col = warp_n + ni*8 + g;
                b[ni][0] = Bs[(kk+tig)*BSTRIDE + col];
                b[ni][1] = Bs[(kk+tig+4)*BSTRIDE + col];
            }
            #pragma unroll
            for (int mi = 0; mi < 2; mi++)
                #pragma unroll
                for (int ni = 0; ni < 4; ni++) mma_tf32(acc[mi][ni], a[mi], b[ni]);
        }
        __syncthreads();
    }
    #pragma unroll
    for (int mi = 0; mi < 2; mi++) {
        #pragma unroll
        for (int ni = 0; ni < 4; ni++) {
            int mrow = warp_m + mi*16 + g;
            int col = n0 + warp_n + ni*8 + 2*tig;
            float4 c = acc[mi][ni];
            if (m0 + mrow < cnt)
                *(float2*)&g_pairout[(long)(base+m0+mrow)*H + col] = make_float2(c.x, c.y);
            if (m0 + mrow + 8 < cnt)
                *(float2*)&g_pairout[(long)(base+m0+mrow+8)*H + col] = make_float2(c.z, c.w);
        }
    }
}

// ---------------- shared-FFN activation ----------------
__global__ void silumul_kernel(float* __restrict__ g, const float* __restrict__ u, int n) {
    int i = blockIdx.x*256 + threadIdx.x;
    if (i < n) {
        float x = g[i];
        g[i] = (x / (1.f + expf(-x))) * u[i];
    }
}

// ---------------- final combine ----------------
__global__ void combine_kernel(float* __restrict__ out) {
    int t = blockIdx.x;
    int pos[TOPK]; float w[TOPK];
    #pragma unroll
    for (int j = 0; j < TOPK; j++) {
        pos[j] = g_pairPos[t*TOPK + j];
        w[j]   = g_pairW[pos[j]];
    }
    for (int h = threadIdx.x; h < H; h += 256) {
        float s = g_hres[(long)t*H + h] + g_shared[(long)t*H + h];
        #pragma unroll
        for (int j = 0; j < TOPK; j++)
            s += w[j] * g_pairout[(long)pos[j]*H + h];
        out[(long)t*H + h] = s;
    }
}

// ---------------- launch ----------------
extern "C" void kernel_launch(void* const* d_in, const int* in_sizes, int n_in,
                              void* d_out, int out_size) {
    (void)in_sizes; (void)n_in; (void)out_size;
    const float* x       = (const float*)d_in[0];
    const float* ln1     = (const float*)d_in[1];
    const float* ln2     = (const float*)d_in[2];
    const float* Wq      = (const float*)d_in[3];
    const float* Wk      = (const float*)d_in[4];
    const float* Wv      = (const float*)d_in[5];
    const float* Wo      = (const float*)d_in[6];
    const float* gate_w  = (const float*)d_in[7];
    const float* gpe     = (const float*)d_in[8];
    const float* upe     = (const float*)d_in[9];
    const float* dpe     = (const float*)d_in[10];
    const float* sh_gate = (const float*)d_in[11];
    const float* sh_up   = (const float*)d_in[12];
    const float* sh_down = (const float*)d_in[13];
    float* out = (float*)d_out;

    float *h1p,*qp,*kp,*vp,*scoresp,*attnp,*hresp,*h2p,*sgp,*sup,*sharedp,*gpeTp,*upeTp,*dpeTp;
    cudaGetSymbolAddress((void**)&h1p,     g_h1);
    cudaGetSymbolAddress((void**)&qp,      g_q);
    cudaGetSymbolAddress((void**)&kp,      g_k);
    cudaGetSymbolAddress((void**)&vp,      g_v);
    cudaGetSymbolAddress((void**)&scoresp, g_scores);
    cudaGetSymbolAddress((void**)&attnp,   g_attnout);
    cudaGetSymbolAddress((void**)&hresp,   g_hres);
    cudaGetSymbolAddress((void**)&h2p,     g_h2);
    cudaGetSymbolAddress((void**)&sgp,     g_sg);
    cudaGetSymbolAddress((void**)&sup,     g_su);
    cudaGetSymbolAddress((void**)&sharedp, g_shared);
    cudaGetSymbolAddress((void**)&gpeTp,   g_gpeT);
    cudaGetSymbolAddress((void**)&upeTp,   g_upeT);
    cudaGetSymbolAddress((void**)&dpeTp,   g_dpeT);

    const float inv_sqrt_hd = 0.08838834764831845f;

    // attention branch
    rms_kernel<<<T, 256>>>(x, ln1, h1p);
    gemm_tc<<<dim3(H/64, T/64, 1), 128>>>(h1p, H, 0, Wq, H, 0, 0, qp, H, 0, nullptr, 0, T, H, H, 1.f, 0);
    gemm_tc<<<dim3(H/64, T/64, 1), 128>>>(h1p, H, 0, Wk, H, 0, 0, kp, H, 0, nullptr, 0, T, H, H, 1.f, 0);
    gemm_tc<<<dim3(H/64, T/64, 1), 128>>>(h1p, H, 0, Wv, H, 0, 0, vp, H, 0, nullptr, 0, T, H, H, 1.f, 0);
    rope_kernel<<<T, 256>>>();
    gemm_tc<<<dim3(T/64, T/64, NH), 128>>>(qp, H, HD, kp, H, HD, 1,
                                           scoresp, T, (long)T*T, nullptr, 0,
                                           T, T, HD, inv_sqrt_hd, 1);
    attn_softmax<<<dim3(T, NH), 256>>>();
    gemm_tc<<<dim3(HD/64, T/64, NH), 128>>>(scoresp, T, (long)T*T, vp, H, HD, 0,
                                            attnp, H, HD, nullptr, 0,
                                            T, HD, T, 1.f, 0);
    gemm_tc<<<dim3(H/64, T/64, 1), 128>>>(attnp, H, 0, Wo, H, 0, 0, hresp, H, 0, x, 0, T, H, H, 1.f, 0);

    // MoE branch
    rms_kernel<<<T, 256>>>(hresp, ln2, h2p);
    transpose_e<<<dim3(EI/32, H), 256>>>(gpe, gpeTp, H, EI);
    transpose_e<<<dim3(EI/32, H), 256>>>(upe, upeTp, H, EI);
    transpose_e<<<dim3(H/32, EI), 256>>>(dpe, dpeTp, EI, H);
    zero_cnt_kernel<<<1, 64>>>();
    router_kernel<<<T, 64>>>(gate_w);
    prefix_kernel<<<1, 32>>>();
    scatter_kernel<<<(NPAIR + 255)/256, 256>>>();
    moe_pass1<<<dim3(EI/64, T/64, NEXP), 128>>>();
    moe_pass2<<<dim3(H/64, T/64, NEXP), 128>>>();

    // shared FFN
    gemm_tc<<<dim3(SHF/64, T/64, 1), 128>>>(h2p, H, 0, sh_gate, SHF, 0, 0, sgp, SHF, 0, nullptr, 0, T, SHF, H, 1.f, 0);
    gemm_tc<<<dim3(SHF/64, T/64, 1), 128>>>(h2p, H, 0, sh_up,   SHF, 0, 0, sup, SHF, 0, nullptr, 0, T, SHF, H, 1.f, 0);
    silumul_kernel<<<(T*SHF + 255)/256, 256>>>(sgp, sup, T*SHF);
    gemm_tc<<<dim3(H/64, T/64, 1), 128>>>(sgp, SHF, 0, sh_down, H, 0, 0, sharedp, H, 0, nullptr, 0, T, H, SHF, 1.f, 0);

    // combine
    combine_kernel<<<T, 256>>>(out);
}

// round 3
// speedup vs baseline: 2.3092x; 1.2518x over previous
#include <cuda_runtime.h>
#include <math.h>

#define T 1024
#define H 1280
#define NH 10
#define HD 128
#define EI 896
#define NEXP 64
#define TOPK 6
#define SHF 1792
#define NPAIR (T*TOPK)

// ---------------- device scratch ----------------
static __device__ float g_h1[T*H];
static __device__ float g_q[T*H];
static __device__ float g_k[T*H];
static __device__ float g_v[T*H];
static __device__ float g_scores[NH*T*T];
static __device__ float g_attnout[T*H];
static __device__ float g_hres[T*H];
static __device__ float g_h2[T*H];
static __device__ float g_sg[T*SHF];
static __device__ float g_su[T*SHF];
static __device__ float g_shared[T*H];
static __device__ float g_gpeT[(size_t)NEXP*H*EI];
static __device__ float g_upeT[(size_t)NEXP*H*EI];
static __device__ float g_dpeT[(size_t)NEXP*EI*H];
static __device__ float g_act[(size_t)(NPAIR+64)*EI];
static __device__ float g_pairout[(size_t)NPAIR*H];
static __device__ int   g_cnt[NEXP];
static __device__ int   g_off[NEXP];
static __device__ int   g_cur[NEXP];
static __device__ int   g_tokE[NPAIR];
static __device__ float g_tokW[NPAIR];
static __device__ int   g_pairTok[NPAIR];
static __device__ float g_pairW[NPAIR];
static __device__ int   g_pairPos[NPAIR];

// ---------------- helpers ----------------
__device__ __forceinline__ void mma_tf32(float4& c, const unsigned a[4], const unsigned b[2]) {
    asm volatile("mma.sync.aligned.m16n8k8.row.col.f32.tf32.tf32.f32 "
        "{%0,%1,%2,%3}, {%4,%5,%6,%7}, {%8,%9}, {%0,%1,%2,%3};"
        : "+f"(c.x), "+f"(c.y), "+f"(c.z), "+f"(c.w)
        : "r"(a[0]), "r"(a[1]), "r"(a[2]), "r"(a[3]), "r"(b[0]), "r"(b[1]));
}
__device__ __forceinline__ void cp16(const void* smem, const void* gmem) {
    unsigned sa = (unsigned)__cvta_generic_to_shared(smem);
    asm volatile("cp.async.cg.shared.global [%0], [%1], 16;" :: "r"(sa), "l"(gmem));
}
#define CP_COMMIT asm volatile("cp.async.commit_group;")
#define CP_WAIT1  asm volatile("cp.async.wait_group 1;")

#define ASTRIDE 36
#define BSTRIDE 72
#define ASTRIDE16 20

// ---------------- RMSNorm ----------------
__global__ void rms_kernel(const float* __restrict__ x, const float* __restrict__ w,
                           float* __restrict__ out) {
    int t = blockIdx.x;
    const float* xr = x + (long)t*H;
    __shared__ float red[256];
    float s = 0.f;
    for (int i = threadIdx.x; i < H; i += 256) { float v = xr[i]; s += v*v; }
    red[threadIdx.x] = s; __syncthreads();
    for (int k = 128; k > 0; k >>= 1) {
        if (threadIdx.x < k) red[threadIdx.x] += red[threadIdx.x + k];
        __syncthreads();
    }
    float r = rsqrtf(red[0]/(float)H + 1e-6f);
    for (int i = threadIdx.x; i < H; i += 256) out[(long)t*H + i] = w[i]*xr[i]*r;
}

// ---------------- pipelined tf32 GEMM: C = alpha*A@B (+res) -----------------
// 64x64x32 tiles, 128 threads, 2-stage cp.async pipeline.
// mode: 0 none, 1 causal block skip, 2 K capped at m0+64.
// If Bb!=null: z selects (B,C) from {(B,C),(Bb,Cb),(Bc,Cc)}; else batch via strides.
__global__ void __launch_bounds__(128)
gemm_tc(const float* __restrict__ A, int lda, long sA,
        const float* __restrict__ B, const float* __restrict__ Bb, const float* __restrict__ Bc,
        int ldb, long sB, int transB,
        float* __restrict__ C, float* __restrict__ Cb, float* __restrict__ Cc,
        int ldc, long sC,
        const float* __restrict__ res, long sR,
        int M, int N, int K, float alpha, int mode) {
    int m0 = blockIdx.y*64, n0 = blockIdx.x*64;
    if (mode == 1 && n0 > m0 + 63) return;
    int bz = blockIdx.z;
    A += (long)bz*sA;
    if (Bb) {
        if (bz == 1) { B = Bb; C = Cb; }
        else if (bz == 2) { B = Bc; C = Cc; }
    } else {
        B += (long)bz*sB; C += (long)bz*sC; if (res) res += (long)bz*sR;
    }
    int Klim = (mode == 2) ? (m0 + 64 < K ? m0 + 64 : K) : K;

    __shared__ unsigned As[2][64*ASTRIDE];
    __shared__ unsigned Bs[2][2304];
    int tid = threadIdx.x;
    int lane = tid & 31, warpId = tid >> 5;
    int g = lane >> 2, tig = lane & 3;
    int warp_m = (warpId & 1) * 32, warp_n = (warpId >> 1) * 32;
    float4 acc[2][4];
    #pragma unroll
    for (int i = 0; i < 2; i++)
        #pragma unroll
        for (int j = 0; j < 4; j++) acc[i][j] = make_float4(0.f,0.f,0.f,0.f);

#define G_LOAD(sidx, k0v) do { int _k0 = (k0v); if (_k0 < Klim) { \
    _Pragma("unroll") for (int i = 0; i < 4; i++) { int idx = tid + i*128; int r = idx >> 3, c4 = (idx & 7) << 2; \
        cp16(&As[sidx][r*ASTRIDE + c4], &A[(long)(m0+r)*lda + _k0 + c4]); } \
    if (!transB) { \
        _Pragma("unroll") for (int i = 0; i < 4; i++) { int idx = tid + i*128; int r = idx >> 4, c4 = (idx & 15) << 2; \
            cp16(&Bs[sidx][r*BSTRIDE + c4], &B[(long)(_k0+r)*ldb + n0 + c4]); } \
    } else { \
        _Pragma("unroll") for (int i = 0; i < 4; i++) { int idx = tid + i*128; int r = idx >> 3, c4 = (idx & 7) << 2; \
            cp16(&Bs[sidx][r*ASTRIDE + c4], &B[(long)(n0+r)*ldb + _k0 + c4]); } \
    } } CP_COMMIT; } while(0)

    int nIter = Klim >> 5;
    G_LOAD(0, 0);
    for (int it = 0; it < nIter; it++) {
        int s = it & 1;
        G_LOAD(s ^ 1, (it + 1) << 5);
        CP_WAIT1;
        __syncthreads();
        if (!transB) {
            #pragma unroll
            for (int kk = 0; kk < 32; kk += 8) {
                unsigned a[2][4], b[4][2];
                #pragma unroll
                for (int mi = 0; mi < 2; mi++) {
                    int rb = warp_m + mi*16 + g;
                    a[mi][0] = As[s][rb*ASTRIDE + kk + tig];
                    a[mi][1] = As[s][(rb+8)*ASTRIDE + kk + tig];
                    a[mi][2] = As[s][rb*ASTRIDE + kk + tig + 4];
                    a[mi][3] = As[s][(rb+8)*ASTRIDE + kk + tig + 4];
                }
                #pragma unroll
                for (int ni = 0; ni < 4; ni++) {
                    int col = warp_n + ni*8 + g;
                    b[ni][0] = Bs[s][(kk+tig)*BSTRIDE + col];
                    b[ni][1] = Bs[s][(kk+tig+4)*BSTRIDE + col];
                }
                #pragma unroll
                for (int mi = 0; mi < 2; mi++)
                    #pragma unroll
                    for (int ni = 0; ni < 4; ni++) mma_tf32(acc[mi][ni], a[mi], b[ni]);
            }
        } else {
            #pragma unroll
            for (int kk = 0; kk < 32; kk += 8) {
                unsigned a[2][4], b[4][2];
                #pragma unroll
                for (int mi = 0; mi < 2; mi++) {
                    int rb = warp_m + mi*16 + g;
                    a[mi][0] = As[s][rb*ASTRIDE + kk + tig];
                    a[mi][1] = As[s][(rb+8)*ASTRIDE + kk + tig];
                    a[mi][2] = As[s][rb*ASTRIDE + kk + tig + 4];
                    a[mi][3] = As[s][(rb+8)*ASTRIDE + kk + tig + 4];
                }
                #pragma unroll
                for (int ni = 0; ni < 4; ni++) {
                    int col = warp_n + ni*8 + g;
                    b[ni][0] = Bs[s][col*ASTRIDE + kk + tig];
                    b[ni][1] = Bs[s][col*ASTRIDE + kk + tig + 4];
                }
                #pragma unroll
                for (int mi = 0; mi < 2; mi++)
                    #pragma unroll
                    for (int ni = 0; ni < 4; ni++) mma_tf32(acc[mi][ni], a[mi], b[ni]);
            }
        }
        __syncthreads();
    }
#undef G_LOAD
    #pragma unroll
    for (int mi = 0; mi < 2; mi++) {
        #pragma unroll
        for (int ni = 0; ni < 4; ni++) {
            int row = m0 + warp_m + mi*16 + g;
            int col = n0 + warp_n + ni*8 + 2*tig;
            float4 c = acc[mi][ni];
            float2 v0 = { alpha*c.x, alpha*c.y };
            float2 v1 = { alpha*c.z, alpha*c.w };
            if (res) {
                float2 r0 = *(const float2*)&res[(long)row*ldc + col];
                float2 r1 = *(const float2*)&res[(long)(row+8)*ldc + col];
                v0.x += r0.x; v0.y += r0.y; v1.x += r1.x; v1.y += r1.y;
            }
            *(float2*)&C[(long)row*ldc + col] = v0;
            *(float2*)&C[(long)(row+8)*ldc + col] = v1;
        }
    }
}

// ---------------- RoPE ----------------
__global__ void rope_kernel() {
    int t = blockIdx.x, tid = threadIdx.x;
    __shared__ float cs[64], sn[64];
    if (tid < 64) {
        float inv = powf(10000.0f, -(float)tid / 64.0f);
        float fr = (float)t * inv;
        cs[tid] = cosf(fr); sn[tid] = sinf(fr);
    }
    __syncthreads();
    for (int idx = tid; idx < NH*64; idx += 256) {
        int hh = idx >> 6, j = idx & 63;
        long b = (long)t*H + hh*HD;
        float c = cs[j], s = sn[j];
        float q1 = g_q[b+j], q2 = g_q[b+j+64];
        g_q[b+j]    = q1*c - q2*s;
        g_q[b+j+64] = q2*c + q1*s;
        float k1 = g_k[b+j], k2 = g_k[b+j+64];
        g_k[b+j]    = k1*c - k2*s;
        g_k[b+j+64] = k2*c + k1*s;
    }
}

// ---------------- causal softmax (zero only to next 64-boundary) ----------------
__global__ void attn_softmax() {
    int t = blockIdx.x, hh = blockIdx.y, tid = threadIdx.x;
    float* row = g_scores + ((long)hh*T + t)*(long)T;
    int len = t + 1;
    int zend = ((t >> 6) + 1) << 6;
    __shared__ float red[256];
    float mx = -3.0e38f;
    for (int i = tid; i < len; i += 256) mx = fmaxf(mx, row[i]);
    red[tid] = mx; __syncthreads();
    for (int s = 128; s > 0; s >>= 1) { if (tid < s) red[tid] = fmaxf(red[tid], red[tid+s]); __syncthreads(); }
    mx = red[0]; __syncthreads();
    float sum = 0.f;
    for (int i = tid; i < len; i += 256) { float e = expf(row[i]-mx); row[i] = e; sum += e; }
    red[tid] = sum; __syncthreads();
    for (int s = 128; s > 0; s >>= 1) { if (tid < s) red[tid] += red[tid+s]; __syncthreads(); }
    float inv = 1.0f / red[0];
    for (int i = tid; i < len; i += 256) row[i] *= inv;
    for (int i = len + tid; i < zend; i += 256) row[i] = 0.f;
}

// ---------------- expert-last transpose: in[R][C][64] -> out[64][R][C] ----------------
__global__ void transpose_e(const float* __restrict__ in, float* __restrict__ out, int R, int C) {
    int r = blockIdx.y;
    int c0 = blockIdx.x * 32;
    __shared__ float tile[64*33];
    const float* src = in + ((long)r*C + c0)*64;
    for (int i = threadIdx.x; i < 2048; i += 256) {
        int ci = i >> 6, e = i & 63;
        tile[e*33 + ci] = src[i];
    }
    __syncthreads();
    for (int i = threadIdx.x; i < 2048; i += 256) {
        int e = i >> 5, ci = i & 31;
        out[(long)e*R*C + (long)r*C + c0 + ci] = tile[e*33 + ci];
    }
}

// ---------------- router ----------------
__global__ void zero_cnt_kernel() { if (threadIdx.x < NEXP) g_cnt[threadIdx.x] = 0; }

__global__ void router_kernel(const float* __restrict__ gw) {
    int t = blockIdx.x, e = threadIdx.x;
    const float* hr = g_h2 + (long)t*H;
    float s = 0.f;
    for (int h = 0; h < H; h++) s += hr[h] * gw[h*NEXP + e];
    __shared__ float probs[NEXP];
    probs[e] = s;
    __syncthreads();
    if (e == 0) {
        float mx = -3e38f;
        for (int i = 0; i < NEXP; i++) mx = fmaxf(mx, probs[i]);
        float sum = 0.f;
        for (int i = 0; i < NEXP; i++) { probs[i] = expf(probs[i]-mx); sum += probs[i]; }
        float inv = 1.f/sum;
        for (int i = 0; i < NEXP; i++) probs[i] *= inv;
        int ti[TOPK]; float tw[TOPK]; float ws = 0.f;
        for (int j = 0; j < TOPK; j++) {
            int bi = 0; float bv = -1.f;
            for (int i = 0; i < NEXP; i++) if (probs[i] > bv) { bv = probs[i]; bi = i; }
            ti[j] = bi; tw[j] = bv; ws += bv; probs[bi] = -2.f;
        }
        float wi = 1.f/ws;
        for (int j = 0; j < TOPK; j++) {
            g_tokE[t*TOPK+j] = ti[j];
            g_tokW[t*TOPK+j] = tw[j]*wi;
            atomicAdd(&g_cnt[ti[j]], 1);
        }
    }
}

__global__ void prefix_kernel() {
    if (threadIdx.x == 0) {
        int s = 0;
        for (int e = 0; e < NEXP; e++) { g_off[e] = s; g_cur[e] = s; s += g_cnt[e]; }
    }
}

__global__ void scatter_kernel() {
    int i = blockIdx.x*256 + threadIdx.x;
    if (i < NPAIR) {
        int e = g_tokE[i];
        int pos = atomicAdd(&g_cur[e], 1);
        g_pairTok[pos] = i / TOPK;
        g_pairW[pos]   = g_tokW[i];
        g_pairPos[i]   = pos;
    }
}

// ---------------- MoE pass 1 (pipelined, BK=16, dual-B) ----------------
__global__ void __launch_bounds__(128) moe_pass1() {
    int e = blockIdx.z;
    int cnt = g_cnt[e];
    int m0 = blockIdx.y * 64;
    if (m0 >= cnt) return;
    int n0 = blockIdx.x * 64;
    int base = g_off[e];
    const float* Bg = g_gpeT + (size_t)e*H*EI;
    const float* Bu = g_upeT + (size_t)e*H*EI;
    __shared__ int stok[64];
    __shared__ unsigned As[2][64*ASTRIDE16];
    __shared__ unsigned Bs1[2][16*BSTRIDE];
    __shared__ unsigned Bs2[2][16*BSTRIDE];
    int tid = threadIdx.x;
    int lane = tid & 31, warpId = tid >> 5;
    int g = lane >> 2, tig = lane & 3;
    int warp_m = (warpId & 1) * 32, warp_n = (warpId >> 1) * 32;
    if (tid < 64) stok[tid] = (m0 + tid < cnt) ? g_pairTok[base + m0 + tid] : 0;
    __syncthreads();
    float4 accG[2][4], accU[2][4];
    #pragma unroll
    for (int i = 0; i < 2; i++)
        #pragma unroll
        for (int j = 0; j < 4; j++) { accG[i][j] = make_float4(0,0,0,0); accU[i][j] = make_float4(0,0,0,0); }

#define P1_LOAD(sidx, k0v) do { int _k0 = (k0v); if (_k0 < H) { \
    _Pragma("unroll") for (int i = 0; i < 2; i++) { int idx = tid + i*128; int r = idx >> 2, c4 = (idx & 3) << 2; \
        cp16(&As[sidx][r*ASTRIDE16 + c4], &g_h2[(long)stok[r]*H + _k0 + c4]); } \
    _Pragma("unroll") for (int i = 0; i < 2; i++) { int idx = tid + i*128; int r = idx >> 4, c4 = (idx & 15) << 2; \
        cp16(&Bs1[sidx][r*BSTRIDE + c4], &Bg[(long)(_k0+r)*EI + n0 + c4]); \
        cp16(&Bs2[sidx][r*BSTRIDE + c4], &Bu[(long)(_k0+r)*EI + n0 + c4]); } \
    } CP_COMMIT; } while(0)

    P1_LOAD(0, 0);
    const int nIter = H / 16;
    for (int it = 0; it < nIter; it++) {
        int s = it & 1;
        P1_LOAD(s ^ 1, (it + 1) << 4);
        CP_WAIT1;
        __syncthreads();
        #pragma unroll
        for (int kk = 0; kk < 16; kk += 8) {
            unsigned a[2][4], b1[4][2], b2[4][2];
            #pragma unroll
            for (int mi = 0; mi < 2; mi++) {
                int rb = warp_m + mi*16 + g;
                a[mi][0] = As[s][rb*ASTRIDE16 + kk + tig];
                a[mi][1] = As[s][(rb+8)*ASTRIDE16 + kk + tig];
                a[mi][2] = As[s][rb*ASTRIDE16 + kk + tig + 4];
                a[mi][3] = As[s][(rb+8)*ASTRIDE16 + kk + tig + 4];
            }
            #pragma unroll
            for (int ni = 0; ni < 4; ni++) {
                int col = warp_n + ni*8 + g;
                b1[ni][0] = Bs1[s][(kk+tig)*BSTRIDE + col];
                b1[ni][1] = Bs1[s][(kk+tig+4)*BSTRIDE + col];
                b2[ni][0] = Bs2[s][(kk+tig)*BSTRIDE + col];
                b2[ni][1] = Bs2[s][(kk+tig+4)*BSTRIDE + col];
            }
            #pragma unroll
            for (int mi = 0; mi < 2; mi++)
                #pragma unroll
                for (int ni = 0; ni < 4; ni++) {
                    mma_tf32(accG[mi][ni], a[mi], b1[ni]);
                    mma_tf32(accU[mi][ni], a[mi], b2[ni]);
                }
        }
        __syncthreads();
    }
#undef P1_LOAD
    #pragma unroll
    for (int mi = 0; mi < 2; mi++) {
        #pragma unroll
        for (int ni = 0; ni < 4; ni++) {
            int mrow = warp_m + mi*16 + g;
            int col = n0 + warp_n + ni*8 + 2*tig;
            float4 cg = accG[mi][ni], cu = accU[mi][ni];
            if (m0 + mrow < cnt) {
                float g0 = cg.x, g1 = cg.y;
                float2 v = { (g0/(1.f+expf(-g0)))*cu.x, (g1/(1.f+expf(-g1)))*cu.y };
                *(float2*)&g_act[(long)(base+m0+mrow)*EI + col] = v;
            }
            if (m0 + mrow + 8 < cnt) {
                float g0 = cg.z, g1 = cg.w;
                float2 v = { (g0/(1.f+expf(-g0)))*cu.z, (g1/(1.f+expf(-g1)))*cu.w };
                *(float2*)&g_act[(long)(base+m0+mrow+8)*EI + col] = v;
            }
        }
    }
}

// ---------------- MoE pass 2 (pipelined, BK=32) ----------------
__global__ void __launch_bounds__(128) moe_pass2() {
    int e = blockIdx.z;
    int cnt = g_cnt[e];
    int m0 = blockIdx.y * 64;
    if (m0 >= cnt) return;
    int n0 = blockIdx.x * 64;
    int base = g_off[e];
    const float* Bm = g_dpeT + (size_t)e*EI*H;
    const float* Arows = g_act + (long)(base+m0)*EI;
    __shared__ unsigned As[2][64*ASTRIDE];
    __shared__ unsigned Bs[2][32*BSTRIDE];
    int tid = threadIdx.x;
    int lane = tid & 31, warpId = tid >> 5;
    int g = lane >> 2, tig = lane & 3;
    int warp_m = (warpId & 1) * 32, warp_n = (warpId >> 1) * 32;
    float4 acc[2][4];
    #pragma unroll
    for (int i = 0; i < 2; i++)
        #pragma unroll
        for (int j = 0; j < 4; j++) acc[i][j] = make_float4(0,0,0,0);

#define P2_LOAD(sidx, k0v) do { int _k0 = (k0v); if (_k0 < EI) { \
    _Pragma("unroll") for (int i = 0; i < 4; i++) { int idx = tid + i*128; int r = idx >> 3, c4 = (idx & 7) << 2; \
        cp16(&As[sidx][r*ASTRIDE + c4], &Arows[(long)r*EI + _k0 + c4]); } \
    _Pragma("unroll") for (int i = 0; i < 4; i++) { int idx = tid + i*128; int r = idx >> 4, c4 = (idx & 15) << 2; \
        cp16(&Bs[sidx][r*BSTRIDE + c4], &Bm[(long)(_k0+r)*H + n0 + c4]); } \
    } CP_COMMIT; } while(0)

    P2_LOAD(0, 0);
    const int nIter = EI / 32;
    for (int it = 0; it < nIter; it++) {
        int s = it & 1;
        P2_LOAD(s ^ 1, (it + 1) << 5);
        CP_WAIT1;
        __syncthreads();
        #pragma unroll
        for (int kk = 0; kk < 32; kk += 8) {
            unsigned a[2][4], b[4][2];
            #pragma unroll
            for (int mi = 0; mi < 2; mi++) {
                int rb = warp_m + mi*16 + g;
                a[mi][0] = As[s][rb*ASTRIDE + kk + tig];
                a[mi][1] = As[s][(rb+8)*ASTRIDE + kk + tig];
                a[mi][2] = As[s][rb*ASTRIDE + kk + tig + 4];
                a[mi][3] = As[s][(rb+8)*ASTRIDE + kk + tig + 4];
            }
            #pragma unroll
            for (int ni = 0; ni < 4; ni++) {
                int col = warp_n + ni*8 + g;
                b[ni][0] = Bs[s][(kk+tig)*BSTRIDE + col];
                b[ni][1] = Bs[s][(kk+tig+4)*BSTRIDE + col];
            }
            #pragma unroll
            for (int mi = 0; mi < 2; mi++)
                #pragma unroll
                for (int ni = 0; ni < 4; ni++) mma_tf32(acc[mi][ni], a[mi], b[ni]);
        }
        __syncthreads();
    }
#undef P2_LOAD
    #pragma unroll
    for (int mi = 0; mi < 2; mi++) {
        #pragma unroll
        for (int ni = 0; ni < 4; ni++) {
            int mrow = warp_m + mi*16 + g;
            int col = n0 + warp_n + ni*8 + 2*tig;
            float4 c = acc[mi][ni];
            if (m0 + mrow < cnt)
                *(float2*)&g_pairout[(long)(base+m0+mrow)*H + col] = make_float2(c.x, c.y);
            if (m0 + mrow + 8 < cnt)
                *(float2*)&g_pairout[(long)(base+m0+mrow+8)*H + col] = make_float2(c.z, c.w);
        }
    }
}

// ---------------- shared-FFN activation ----------------
__global__ void silumul_kernel(float* __restrict__ g, const float* __restrict__ u, int n) {
    int i = blockIdx.x*256 + threadIdx.x;
    if (i < n) {
        float x = g[i];
        g[i] = (x / (1.f + expf(-x))) * u[i];
    }
}

// ---------------- final combine ----------------
__global__ void combine_kernel(float* __restrict__ out) {
    int t = blockIdx.x;
    int pos[TOPK]; float w[TOPK];
    #pragma unroll
    for (int j = 0; j < TOPK; j++) {
        pos[j] = g_pairPos[t*TOPK + j];
        w[j]   = g_pairW[pos[j]];
    }
    for (int h = threadIdx.x; h < H; h += 256) {
        float s = g_hres[(long)t*H + h] + g_shared[(long)t*H + h];
        #pragma unroll
        for (int j = 0; j < TOPK; j++)
            s += w[j] * g_pairout[(long)pos[j]*H + h];
        out[(long)t*H + h] = s;
    }
}

// ---------------- launch ----------------
extern "C" void kernel_launch(void* const* d_in, const int* in_sizes, int n_in,
                              void* d_out, int out_size) {
    (void)in_sizes; (void)n_in; (void)out_size;
    const float* x       = (const float*)d_in[0];
    const float* ln1     = (const float*)d_in[1];
    const float* ln2     = (const float*)d_in[2];
    const float* Wq      = (const float*)d_in[3];
    const float* Wk      = (const float*)d_in[4];
    const float* Wv      = (const float*)d_in[5];
    const float* Wo      = (const float*)d_in[6];
    const float* gate_w  = (const float*)d_in[7];
    const float* gpe     = (const float*)d_in[8];
    const float* upe     = (const float*)d_in[9];
    const float* dpe     = (const float*)d_in[10];
    const float* sh_gate = (const float*)d_in[11];
    const float* sh_up   = (const float*)d_in[12];
    const float* sh_down = (const float*)d_in[13];
    float* out = (float*)d_out;

    float *h1p,*qp,*kp,*vp,*scoresp,*attnp,*hresp,*h2p,*sgp,*sup,*sharedp,*gpeTp,*upeTp,*dpeTp;
    cudaGetSymbolAddress((void**)&h1p,     g_h1);
    cudaGetSymbolAddress((void**)&qp,      g_q);
    cudaGetSymbolAddress((void**)&kp,      g_k);
    cudaGetSymbolAddress((void**)&vp,      g_v);
    cudaGetSymbolAddress((void**)&scoresp, g_scores);
    cudaGetSymbolAddress((void**)&attnp,   g_attnout);
    cudaGetSymbolAddress((void**)&hresp,   g_hres);
    cudaGetSymbolAddress((void**)&h2p,     g_h2);
    cudaGetSymbolAddress((void**)&sgp,     g_sg);
    cudaGetSymbolAddress((void**)&sup,     g_su);
    cudaGetSymbolAddress((void**)&sharedp, g_shared);
    cudaGetSymbolAddress((void**)&gpeTp,   g_gpeT);
    cudaGetSymbolAddress((void**)&upeTp,   g_upeT);
    cudaGetSymbolAddress((void**)&dpeTp,   g_dpeT);

    const float inv_sqrt_hd = 0.08838834764831845f;

    // attention branch
    rms_kernel<<<T, 256>>>(x, ln1, h1p);
    // fused QKV: z=3 selects (Wq,gq),(Wk,gk),(Wv,gv)
    gemm_tc<<<dim3(H/64, T/64, 3), 128>>>(h1p, H, 0, Wq, Wk, Wv, H, 0, 0,
                                          qp, kp, vp, H, 0, nullptr, 0,
                                          T, H, H, 1.f, 0);
    rope_kernel<<<T, 256>>>();
    gemm_tc<<<dim3(T/64, T/64, NH), 128>>>(qp, H, HD, kp, nullptr, nullptr, H, HD, 1,
                                           scoresp, nullptr, nullptr, T, (long)T*T, nullptr, 0,
                                           T, T, HD, inv_sqrt_hd, 1);
    attn_softmax<<<dim3(T, NH), 256>>>();
    gemm_tc<<<dim3(HD/64, T/64, NH), 128>>>(scoresp, T, (long)T*T, vp, nullptr, nullptr, H, HD, 0,
                                            attnp, nullptr, nullptr, H, HD, nullptr, 0,
                                            T, HD, T, 1.f, 2);
    gemm_tc<<<dim3(H/64, T/64, 1), 128>>>(attnp, H, 0, Wo, nullptr, nullptr, H, 0, 0,
                                          hresp, nullptr, nullptr, H, 0, x, 0,
                                          T, H, H, 1.f, 0);

    // MoE branch
    rms_kernel<<<T, 256>>>(hresp, ln2, h2p);
    transpose_e<<<dim3(EI/32, H), 256>>>(gpe, gpeTp, H, EI);
    transpose_e<<<dim3(EI/32, H), 256>>>(upe, upeTp, H, EI);
    transpose_e<<<dim3(H/32, EI), 256>>>(dpe, dpeTp, EI, H);
    zero_cnt_kernel<<<1, 64>>>();
    router_kernel<<<T, 64>>>(gate_w);
    prefix_kernel<<<1, 32>>>();
    scatter_kernel<<<(NPAIR + 255)/256, 256>>>();
    moe_pass1<<<dim3(EI/64, T/64, NEXP), 128>>>();
    moe_pass2<<<dim3(H/64, T/64, NEXP), 128>>>();

    // shared FFN: fused gate+up via z=2
    gemm_tc<<<dim3(SHF/64, T/64, 2), 128>>>(h2p, H, 0, sh_gate, sh_up, nullptr, SHF, 0, 0,
                                            sgp, sup, nullptr, SHF, 0, nullptr, 0,
                                            T, SHF, H, 1.f, 0);
    silumul_kernel<<<(T*SHF + 255)/256, 256>>>(sgp, sup, T*SHF);
    gemm_tc<<<dim3(H/64, T/64, 1), 128>>>(sgp, SHF, 0, sh_down, nullptr, nullptr, H, 0, 0,
                                          sharedp, nullptr, nullptr, H, 0, nullptr, 0,
                                          T, H, SHF, 1.f, 0);

    // combine
    combine_kernel<<<T, 256>>>(out);
}